// round 16
// baseline (speedup 1.0000x reference)
#include <cuda_runtime.h>
#include <cuda_fp16.h>
#include <cstdint>
#include <math.h>

#define D_IN  256
#define D_H   512
#define D_OUT 256
#define NB    8
#define ROWS  (9 * 32768)

#define MT  128    // M tile (per m-step)
#define NTT 128    // CTA N tile
#define KC  64     // K chunk (halves) = 128 B/row
#define MSTEPS 8   // m-tiles per CTA (both GEMMs)

// Scratch (allocation-free rule)
__device__ __half g_Xn [(size_t)ROWS * D_IN];
__device__ __half g_H  [(size_t)ROWS * D_H];
__device__ __half g_F  [(size_t)ROWS * D_OUT];   // fp16 glue buffer
__device__ __half g_W1T[(size_t)D_H * D_IN];     // [N=512][K=256]
__device__ __half g_W2T[(size_t)D_OUT * D_H];    // [N=256][K=512]

// ---------------------------------------------------------------------------
__device__ __forceinline__ uint32_t smem_u32(const void* p) {
    uint32_t a;
    asm("{ .reg .u64 t; cvta.to.shared.u64 t, %1; cvt.u32.u64 %0, t; }" : "=r"(a) : "l"(p));
    return a;
}
__device__ __forceinline__ void cpa16(uint32_t s, const void* g) {
    asm volatile("cp.async.cg.shared.global [%0], [%1], 16;" :: "r"(s), "l"(g));
}
__device__ __forceinline__ void ldsm4(uint32_t* r, uint32_t addr) {
    asm volatile("ldmatrix.sync.aligned.m8n8.x4.shared.b16 {%0,%1,%2,%3}, [%4];"
                 : "=r"(r[0]), "=r"(r[1]), "=r"(r[2]), "=r"(r[3]) : "r"(addr));
}
__device__ __forceinline__ void mma_f16(float* c, const uint32_t* a, const uint32_t* b) {
    asm volatile("mma.sync.aligned.m16n8k16.row.col.f32.f16.f16.f32 "
                 "{%0,%1,%2,%3}, {%4,%5,%6,%7}, {%8,%9}, {%0,%1,%2,%3};"
                 : "+f"(c[0]), "+f"(c[1]), "+f"(c[2]), "+f"(c[3])
                 : "r"(a[0]), "r"(a[1]), "r"(a[2]), "r"(a[3]), "r"(b[0]), "r"(b[1]));
}

#define TILE_BYTES  (MT * KC * 2)        // 16384 (one 128-row x 128B tile)

// ===========================================================================
// GEMM1, B-resident multi-M: CTA = 8 m-tiles x 128 rows x 128 cols.
// smem: B resident 64 KB (all of K=256) + A 2-stage ring 32 KB. 2 CTAs/SM.
// Flat loop over 32 A-chunks (mt = c>>2, kt = c&3); epilogue each 4th chunk.
// ===========================================================================
#define G1_SMEM (4 * TILE_BYTES + 2 * TILE_BYTES)   // 98304

__global__ void __launch_bounds__(128, 2) tc_gemm1(
    const __half* __restrict__ A, const __half* __restrict__ Bt,
    const float* __restrict__ bias, __half* __restrict__ C)
{
    extern __shared__ char smem[];
    uint32_t sb = smem_u32(smem);
    const int tid = threadIdx.x, wid = tid >> 5, lane = tid & 31;
    const int rowbase = blockIdx.y * (MSTEPS * MT);
    const int n0      = blockIdx.x * NTT;

    const uint32_t bres    = sb;                       // B: 4 chunks x 16 KB
    const uint32_t aoff[2] = { sb + 4 * TILE_BYTES, sb + 5 * TILE_BYTES };

    const int lr = tid >> 3;          // base row 0..15, stride 16
    const int lc = tid & 7;           // 16B block (8 halves)
    const __half* Bbase = Bt + (size_t)n0 * D_IN + lc * 8;
    const __half* Abase = A + (size_t)rowbase * D_IN + lc * 8;

    // resident B (one group)
    {
#pragma unroll
        for (int kt = 0; kt < 4; kt++) {
            const __half* Bp = Bbase + kt * KC;
#pragma unroll
            for (int i = 0; i < 8; i++) {
                int r = lr + i * 16;
                uint32_t so = (uint32_t)(r * 128 + ((lc ^ (r & 7)) << 4));
                cpa16(bres + kt * TILE_BYTES + so, Bp + (size_t)r * D_IN);
            }
        }
        asm volatile("cp.async.commit_group;" ::: "memory");
    }
    auto loadA = [&](int c, int bi) {   // chunk c: mt=c>>2, kt=c&3
        const __half* Ap = Abase + (size_t)(c >> 2) * MT * D_IN + (c & 3) * KC;
#pragma unroll
        for (int i = 0; i < 8; i++) {
            int r = lr + i * 16;
            uint32_t so = (uint32_t)(r * 128 + ((lc ^ (r & 7)) << 4));
            cpa16(aoff[bi] + so, Ap + (size_t)r * D_IN);
        }
        asm volatile("cp.async.commit_group;" ::: "memory");
    };
    loadA(0, 0);

    const int wm = (wid >> 1) * 64;
    const int wn = (wid & 1) * 64;
    const int q = lane >> 3;
    const int arow_base = wm + (q & 1) * 8 + (lane & 7);
    const int acb_add   = q >> 1;
    const int brow_base = wn + (q >> 1) * 8 + (lane & 7);
    const int bcb_add   = q & 1;
    const int g = lane >> 2, cpair = (lane & 3) * 2;

    float acc[4][8][4];
#pragma unroll
    for (int i = 0; i < 4; i++)
#pragma unroll
        for (int j = 0; j < 8; j++)
#pragma unroll
            for (int c = 0; c < 4; c++) acc[i][j][c] = 0.0f;

    const int NCH = MSTEPS * 4;       // 32 A-chunks
    for (int c = 0; c < NCH; c++) {
        int b = c & 1;
        if (c + 1 < NCH) {
            loadA(c + 1, b ^ 1);
            asm volatile("cp.async.wait_group 1;" ::: "memory");
        } else {
            asm volatile("cp.async.wait_group 0;" ::: "memory");
        }
        __syncthreads();

        const uint32_t bchunk = bres + (uint32_t)(c & 3) * TILE_BYTES;
#pragma unroll
        for (int s = 0; s < 4; s++) {
            uint32_t af[4][4], bf[4][4];
#pragma unroll
            for (int i = 0; i < 4; i++) {
                int r = arow_base + i * 16;
                int cb = (2 * s + acb_add) ^ (r & 7);
                ldsm4(af[i], aoff[b] + (uint32_t)(r * 128 + cb * 16));
            }
#pragma unroll
            for (int j2 = 0; j2 < 4; j2++) {
                int r = brow_base + j2 * 16;
                int cb = (2 * s + bcb_add) ^ (r & 7);
                ldsm4(bf[j2], bchunk + (uint32_t)(r * 128 + cb * 16));
            }
#pragma unroll
            for (int i = 0; i < 4; i++)
#pragma unroll
                for (int j = 0; j < 8; j++)
                    mma_f16(acc[i][j], af[i], &bf[j >> 1][(j & 1) * 2]);
        }

        if ((c & 3) == 3) {
            int row0 = rowbase + (c >> 2) * MT;
#pragma unroll
            for (int j = 0; j < 8; j++) {
                int col = n0 + wn + j * 8 + cpair;
                float b0 = __ldg(bias + col), b1 = __ldg(bias + col + 1);
#pragma unroll
                for (int i = 0; i < 4; i++) {
                    int r = row0 + wm + i * 16 + g;
                    float v0 = fmaxf(acc[i][j][0] + b0, 0.0f);
                    float v1 = fmaxf(acc[i][j][1] + b1, 0.0f);
                    float v2 = fmaxf(acc[i][j][2] + b0, 0.0f);
                    float v3 = fmaxf(acc[i][j][3] + b1, 0.0f);
                    *reinterpret_cast<__half2*>(C + (size_t)r * D_H + col)
                        = __floats2half2_rn(v0, v1);
                    *reinterpret_cast<__half2*>(C + (size_t)(r + 8) * D_H + col)
                        = __floats2half2_rn(v2, v3);
                }
            }
#pragma unroll
            for (int i = 0; i < 4; i++)
#pragma unroll
                for (int j = 0; j < 8; j++)
#pragma unroll
                    for (int cc = 0; cc < 4; cc++) acc[i][j][cc] = 0.0f;
        }
        __syncthreads();
    }
}

// ===========================================================================
// GEMM2 multi-M: CTA = 8 m-tiles x 128 rows x 128 cols over K=512.
// Streams A+B (B chunks re-read from L2; W2T fully L2-resident).
// 2-stage/2-sync ring; flat 64-chunk loop, epilogue each 8th chunk.
// ===========================================================================
#define STAGE_BYTES (2 * TILE_BYTES)     // 32768
#define SM_TOTAL    (2 * STAGE_BYTES)    // 65536

__global__ void __launch_bounds__(128, 2) tc_gemm2(
    const __half* __restrict__ A, const __half* __restrict__ Bt,
    const float* __restrict__ bias, __half* __restrict__ C)
{
    extern __shared__ char smem[];
    uint32_t sb = smem_u32(smem);
    const int tid = threadIdx.x, wid = tid >> 5, lane = tid & 31;
    const int rowbase = blockIdx.y * (MSTEPS * MT);
    const int n0      = blockIdx.x * NTT;

    const uint32_t aoff[2] = { sb,              sb + STAGE_BYTES };
    const uint32_t boff[2] = { sb + TILE_BYTES, sb + STAGE_BYTES + TILE_BYTES };

    const int lr = tid >> 3;
    const int lc = tid & 7;
    const __half* Abase = A  + (size_t)rowbase * D_H + lc * 8;
    const __half* Bbase = Bt + (size_t)n0 * D_H + lc * 8;

    auto load_chunk = [&](int c, int bi) {   // c: mt=c>>3, kt=c&7
        const __half* Ap = Abase + (size_t)(c >> 3) * MT * D_H + (c & 7) * KC;
        const __half* Bp = Bbase + (c & 7) * KC;
#pragma unroll
        for (int i = 0; i < 8; i++) {
            int r = lr + i * 16;
            uint32_t so = (uint32_t)(r * 128 + ((lc ^ (r & 7)) << 4));
            cpa16(aoff[bi] + so, Ap + (size_t)r * D_H);
            cpa16(boff[bi] + so, Bp + (size_t)r * D_H);
        }
        asm volatile("cp.async.commit_group;" ::: "memory");
    };

    const int wm = (wid >> 1) * 64;
    const int wn = (wid & 1) * 64;
    const int q = lane >> 3;
    const int arow_base = wm + (q & 1) * 8 + (lane & 7);
    const int acb_add   = q >> 1;
    const int brow_base = wn + (q >> 1) * 8 + (lane & 7);
    const int bcb_add   = q & 1;
    const int g = lane >> 2, cpair = (lane & 3) * 2;

    float acc[4][8][4];
#pragma unroll
    for (int i = 0; i < 4; i++)
#pragma unroll
        for (int j = 0; j < 8; j++)
#pragma unroll
            for (int c = 0; c < 4; c++) acc[i][j][c] = 0.0f;

    const int NCH = MSTEPS * 8;       // 64 chunks
    load_chunk(0, 0);

    for (int c = 0; c < NCH; c++) {
        int b = c & 1;
        if (c + 1 < NCH) {
            load_chunk(c + 1, b ^ 1);
            asm volatile("cp.async.wait_group 1;" ::: "memory");
        } else {
            asm volatile("cp.async.wait_group 0;" ::: "memory");
        }
        __syncthreads();

#pragma unroll
        for (int s = 0; s < 4; s++) {
            uint32_t af[4][4], bf[4][4];
#pragma unroll
            for (int i = 0; i < 4; i++) {
                int r = arow_base + i * 16;
                int cb = (2 * s + acb_add) ^ (r & 7);
                ldsm4(af[i], aoff[b] + (uint32_t)(r * 128 + cb * 16));
            }
#pragma unroll
            for (int j2 = 0; j2 < 4; j2++) {
                int r = brow_base + j2 * 16;
                int cb = (2 * s + bcb_add) ^ (r & 7);
                ldsm4(bf[j2], boff[b] + (uint32_t)(r * 128 + cb * 16));
            }
#pragma unroll
            for (int i = 0; i < 4; i++)
#pragma unroll
                for (int j = 0; j < 8; j++)
                    mma_f16(acc[i][j], af[i], &bf[j >> 1][(j & 1) * 2]);
        }

        if ((c & 7) == 7) {
            int row0 = rowbase + (c >> 3) * MT;
#pragma unroll
            for (int j = 0; j < 8; j++) {
                int col = n0 + wn + j * 8 + cpair;
                float b0 = __ldg(bias + col), b1 = __ldg(bias + col + 1);
#pragma unroll
                for (int i = 0; i < 4; i++) {
                    int r = row0 + wm + i * 16 + g;
                    float v0 = acc[i][j][0] + b0, v1 = acc[i][j][1] + b1;
                    float v2 = acc[i][j][2] + b0, v3 = acc[i][j][3] + b1;
                    *reinterpret_cast<__half2*>(C + (size_t)r * D_OUT + col)
                        = __floats2half2_rn(v0, v1);
                    *reinterpret_cast<__half2*>(C + (size_t)(r + 8) * D_OUT + col)
                        = __floats2half2_rn(v2, v3);
                }
            }
#pragma unroll
            for (int i = 0; i < 4; i++)
#pragma unroll
                for (int j = 0; j < 8; j++)
#pragma unroll
                    for (int cc = 0; cc < 4; cc++) acc[i][j][cc] = 0.0f;
        }
        __syncthreads();
    }
}

// ---------------------------------------------------------------------------
// Fused weight transposes (one launch): z=0 -> W1 (256x512), z=1 -> W2 (512x256)
// ---------------------------------------------------------------------------
__global__ __launch_bounds__(256) void transpose_both_kernel(
    const float* __restrict__ W1, __half* __restrict__ W1T,
    const float* __restrict__ W2, __half* __restrict__ W2T)
{
    const float* W;  __half* WT;  int R, Cn;
    if (blockIdx.z == 0) { W = W1; WT = W1T; R = D_IN; Cn = D_H; }
    else                 { W = W2; WT = W2T; R = D_H;  Cn = D_OUT; }
    int bx = blockIdx.x * 32, by = blockIdx.y * 32;
    if (bx >= Cn || by >= R) return;

    __shared__ float t[32][33];
    int x = threadIdx.x & 31, y = threadIdx.x >> 5;
#pragma unroll
    for (int i = 0; i < 32; i += 8)
        t[y + i][x] = W[(size_t)(by + y + i) * Cn + bx + x];
    __syncthreads();
#pragma unroll
    for (int i = 0; i < 32; i += 8)
        WT[(size_t)(bx + y + i) * R + by + x] = __float2half_rn(t[x][y + i]);
}

// ---------------------------------------------------------------------------
// LayerNorm (one warp/row), fp16 output
// ---------------------------------------------------------------------------
__global__ __launch_bounds__(256) void ln_kernel(
    const float* __restrict__ state, const float* __restrict__ nbrs,
    const float* __restrict__ gamma, const float* __restrict__ beta,
    __half* __restrict__ Xn, int B)
{
    int row  = blockIdx.x * 8 + (threadIdx.x >> 5);
    int lane = threadIdx.x & 31;
    const float* x = (row < B) ? state + (size_t)row * D_IN
                               : nbrs + (size_t)(row - B) * D_IN;
    float4 v0 = ((const float4*)x)[lane];
    float4 v1 = ((const float4*)x)[lane + 32];

    float s  = v0.x + v0.y + v0.z + v0.w + v1.x + v1.y + v1.z + v1.w;
    float ss = v0.x*v0.x + v0.y*v0.y + v0.z*v0.z + v0.w*v0.w
             + v1.x*v1.x + v1.y*v1.y + v1.z*v1.z + v1.w*v1.w;
#pragma unroll
    for (int o = 16; o; o >>= 1) {
        s  += __shfl_xor_sync(0xFFFFFFFFu, s,  o);
        ss += __shfl_xor_sync(0xFFFFFFFFu, ss, o);
    }
    float mu   = s * (1.0f / D_IN);
    float var  = ss * (1.0f / D_IN) - mu * mu;
    float rstd = rsqrtf(var + 1e-5f);

    float4 g0 = ((const float4*)gamma)[lane];
    float4 g1 = ((const float4*)gamma)[lane + 32];
    float4 be0 = ((const float4*)beta)[lane];
    float4 be1 = ((const float4*)beta)[lane + 32];

    __half2 h0 = __floats2half2_rn((v0.x - mu) * rstd * g0.x + be0.x,
                                   (v0.y - mu) * rstd * g0.y + be0.y);
    __half2 h1 = __floats2half2_rn((v0.z - mu) * rstd * g0.z + be0.z,
                                   (v0.w - mu) * rstd * g0.w + be0.w);
    __half2 h2 = __floats2half2_rn((v1.x - mu) * rstd * g1.x + be1.x,
                                   (v1.y - mu) * rstd * g1.y + be1.y);
    __half2 h3 = __floats2half2_rn((v1.z - mu) * rstd * g1.z + be1.z,
                                   (v1.w - mu) * rstd * g1.w + be1.w);

    __half* dst = Xn + (size_t)row * D_IN;
    uint2 w0, w1;
    w0.x = *(uint32_t*)&h0;  w0.y = *(uint32_t*)&h1;
    w1.x = *(uint32_t*)&h2;  w1.y = *(uint32_t*)&h3;
    ((uint2*)dst)[lane]      = w0;
    ((uint2*)(dst + 128))[lane] = w1;
}

// ---------------------------------------------------------------------------
// Attention aggregation (one warp/batch element), fp16 F, fp32 math/output.
// ---------------------------------------------------------------------------
__global__ __launch_bounds__(256) void attn_kernel(
    const __half* __restrict__ F, const float* __restrict__ aw,
    const float* __restrict__ ab_ptr, float* __restrict__ out, int B)
{
    int b    = blockIdx.x * 8 + (threadIdx.x >> 5);
    int lane = threadIdx.x & 31;
    float ab = ab_ptr[0];

    float4 w0 = ((const float4*)aw)[lane * 2];
    float4 w1 = ((const float4*)aw)[lane * 2 + 1];

    uint4 lv = ((const uint4*)(F + (size_t)b * D_OUT))[lane];
    float2 l0 = __half22float2(*(__half2*)&lv.x);
    float2 l1 = __half22float2(*(__half2*)&lv.y);
    float2 l2 = __half22float2(*(__half2*)&lv.z);
    float2 l3 = __half22float2(*(__half2*)&lv.w);

    uint4 nf[NB];
    float sc[NB];
#pragma unroll
    for (int n = 0; n < NB; n++) {
        nf[n] = ((const uint4*)(F + ((size_t)(1 + n) * B + b) * D_OUT))[lane];
        float2 a0 = __half22float2(*(__half2*)&nf[n].x);
        float2 a1 = __half22float2(*(__half2*)&nf[n].y);
        float2 a2 = __half22float2(*(__half2*)&nf[n].z);
        float2 a3 = __half22float2(*(__half2*)&nf[n].w);
        float d = a0.x * w0.x + a0.y * w0.y + a1.x * w0.z + a1.y * w0.w
                + a2.x * w1.x + a2.y * w1.y + a3.x * w1.z + a3.y * w1.w;
#pragma unroll
        for (int o = 16; o; o >>= 1) d += __shfl_xor_sync(0xFFFFFFFFu, d, o);
        sc[n] = d + ab;
    }

    float mx = sc[0];
#pragma unroll
    for (int n = 1; n < NB; n++) mx = fmaxf(mx, sc[n]);
    float se = 0.0f;
#pragma unroll
    for (int n = 0; n < NB; n++) { sc[n] = expf(sc[n] - mx); se += sc[n]; }
    float inv = 1.0f / se;

    float o0 = l0.x, o1 = l0.y, o2 = l1.x, o3 = l1.y;
    float o4 = l2.x, o5 = l2.y, o6 = l3.x, o7 = l3.y;
#pragma unroll
    for (int n = 0; n < NB; n++) {
        float wn = sc[n] * inv;
        float2 a0 = __half22float2(*(__half2*)&nf[n].x);
        float2 a1 = __half22float2(*(__half2*)&nf[n].y);
        float2 a2 = __half22float2(*(__half2*)&nf[n].z);
        float2 a3 = __half22float2(*(__half2*)&nf[n].w);
        o0 = fmaf(wn, a0.x, o0);  o1 = fmaf(wn, a0.y, o1);
        o2 = fmaf(wn, a1.x, o2);  o3 = fmaf(wn, a1.y, o3);
        o4 = fmaf(wn, a2.x, o4);  o5 = fmaf(wn, a2.y, o5);
        o6 = fmaf(wn, a3.x, o6);  o7 = fmaf(wn, a3.y, o7);
    }
    float* dst = out + (size_t)b * D_OUT;
    float4 r0 = { o0, o1, o2, o3 }, r1 = { o4, o5, o6, o7 };
    ((float4*)dst)[lane * 2]     = r0;
    ((float4*)dst)[lane * 2 + 1] = r1;
}

// ---------------------------------------------------------------------------
extern "C" void kernel_launch(void* const* d_in, const int* in_sizes, int n_in,
                              void* d_out, int out_size)
{
    const float* state = (const float*)d_in[0];
    const float* nbrs  = (const float*)d_in[1];
    const float* gamma = (const float*)d_in[2];
    const float* beta  = (const float*)d_in[3];
    const float* W1    = (const float*)d_in[4];
    const float* b1    = (const float*)d_in[5];
    const float* W2    = (const float*)d_in[6];
    const float* b2    = (const float*)d_in[7];
    const float* aw    = (const float*)d_in[8];
    const float* ab    = (const float*)d_in[9];
    float* out = (float*)d_out;

    int B = in_sizes[0] / D_IN;   // 32768
    int R = 9 * B;                // 294912

    __half *Xn, *H, *F, *W1T, *W2T;
    cudaGetSymbolAddress((void**)&Xn,  g_Xn);
    cudaGetSymbolAddress((void**)&H,   g_H);
    cudaGetSymbolAddress((void**)&F,   g_F);
    cudaGetSymbolAddress((void**)&W1T, g_W1T);
    cudaGetSymbolAddress((void**)&W2T, g_W2T);

    cudaFuncSetAttribute(tc_gemm1, cudaFuncAttributeMaxDynamicSharedMemorySize, G1_SMEM);
    cudaFuncSetAttribute(tc_gemm2, cudaFuncAttributeMaxDynamicSharedMemorySize, SM_TOTAL);

    transpose_both_kernel<<<dim3(16, 16, 2), 256>>>(W1, W1T, W2, W2T);
    ln_kernel<<<R / 8, 256>>>(state, nbrs, gamma, beta, Xn, B);

    // H = h(relu(Xn @ W1 + b1)) — B-resident, 8 m-tiles per CTA
    tc_gemm1<<<dim3(D_H / NTT, R / (MSTEPS * MT)), 128, G1_SMEM>>>(Xn, W1T, b1, H);
    // F = h(H @ W2 + b2) — 8 m-tiles per CTA, B from L2
    tc_gemm2<<<dim3(D_OUT / NTT, R / (MSTEPS * MT)), 128, SM_TOTAL>>>(H, W2T, b2, F);

    attn_kernel<<<B / 8, 256>>>(F, aw, ab, out, B);
}

// round 17
// speedup vs baseline: 1.0081x; 1.0081x over previous
#include <cuda_runtime.h>
#include <cuda_fp16.h>
#include <cstdint>
#include <math.h>

#define D_IN  256
#define D_H   512
#define D_OUT 256
#define NB    8
#define ROWS  (9 * 32768)

#define MT   128    // M tile (per m-step)
#define NTT  128    // CTA N tile
#define KC   64     // K chunk (halves) = 128 B/row
#define MS1  8      // m-tiles per CTA, GEMM1 (K=256: 4 chunks/m-tile -> 32)
#define MS2  4      // m-tiles per CTA, GEMM2 (K=512: 8 chunks/m-tile -> 32)

// Scratch (allocation-free rule)
__device__ __half g_Xn [(size_t)ROWS * D_IN];
__device__ __half g_H  [(size_t)ROWS * D_H];
__device__ __half g_F  [(size_t)ROWS * D_OUT];   // fp16 glue buffer
__device__ __half g_W1T[(size_t)D_H * D_IN];     // [N=512][K=256]
__device__ __half g_W2T[(size_t)D_OUT * D_H];    // [N=256][K=512]

// ---------------------------------------------------------------------------
__device__ __forceinline__ uint32_t smem_u32(const void* p) {
    uint32_t a;
    asm("{ .reg .u64 t; cvta.to.shared.u64 t, %1; cvt.u32.u64 %0, t; }" : "=r"(a) : "l"(p));
    return a;
}
__device__ __forceinline__ void cpa16(uint32_t s, const void* g) {
    asm volatile("cp.async.cg.shared.global [%0], [%1], 16;" :: "r"(s), "l"(g));
}
__device__ __forceinline__ void ldsm4(uint32_t* r, uint32_t addr) {
    asm volatile("ldmatrix.sync.aligned.m8n8.x4.shared.b16 {%0,%1,%2,%3}, [%4];"
                 : "=r"(r[0]), "=r"(r[1]), "=r"(r[2]), "=r"(r[3]) : "r"(addr));
}
__device__ __forceinline__ void mma_f16(float* c, const uint32_t* a, const uint32_t* b) {
    asm volatile("mma.sync.aligned.m16n8k16.row.col.f32.f16.f16.f32 "
                 "{%0,%1,%2,%3}, {%4,%5,%6,%7}, {%8,%9}, {%0,%1,%2,%3};"
                 : "+f"(c[0]), "+f"(c[1]), "+f"(c[2]), "+f"(c[3])
                 : "r"(a[0]), "r"(a[1]), "r"(a[2]), "r"(a[3]), "r"(b[0]), "r"(b[1]));
}

#define TILE_BYTES  (MT * KC * 2)        // 16384 (one 128-row x 128B tile)
#define STAGE_BYTES (2 * TILE_BYTES)     // 32768
#define SM_TOTAL    (2 * STAGE_BYTES)    // 65536

// ===========================================================================
// GEMM1, streaming multi-M (GEMM2-style clone): CTA = 8 m-tiles x 128 rows
// x 128 cols over K=256. Streams A+B (B chunks re-read from L2; W1T slice
// L2-resident). 2-stage/2-sync ring; flat 32-chunk loop (mt=c>>2, kt=c&3),
// epilogue + ReLU every 4th chunk. 2 CTAs/SM.
// ===========================================================================
__global__ void __launch_bounds__(128, 2) tc_gemm1(
    const __half* __restrict__ A, const __half* __restrict__ Bt,
    const float* __restrict__ bias, __half* __restrict__ C)
{
    extern __shared__ char smem[];
    uint32_t sb = smem_u32(smem);
    const int tid = threadIdx.x, wid = tid >> 5, lane = tid & 31;
    const int rowbase = blockIdx.y * (MS1 * MT);
    const int n0      = blockIdx.x * NTT;

    const uint32_t aoff[2] = { sb,              sb + STAGE_BYTES };
    const uint32_t boff[2] = { sb + TILE_BYTES, sb + STAGE_BYTES + TILE_BYTES };

    const int lr = tid >> 3;
    const int lc = tid & 7;
    const __half* Abase = A  + (size_t)rowbase * D_IN + lc * 8;
    const __half* Bbase = Bt + (size_t)n0 * D_IN + lc * 8;

    auto load_chunk = [&](int c, int bi) {   // c: mt=c>>2, kt=c&3
        const __half* Ap = Abase + (size_t)(c >> 2) * MT * D_IN + (c & 3) * KC;
        const __half* Bp = Bbase + (c & 3) * KC;
#pragma unroll
        for (int i = 0; i < 8; i++) {
            int r = lr + i * 16;
            uint32_t so = (uint32_t)(r * 128 + ((lc ^ (r & 7)) << 4));
            cpa16(aoff[bi] + so, Ap + (size_t)r * D_IN);
            cpa16(boff[bi] + so, Bp + (size_t)r * D_IN);
        }
        asm volatile("cp.async.commit_group;" ::: "memory");
    };

    const int wm = (wid >> 1) * 64;
    const int wn = (wid & 1) * 64;
    const int q = lane >> 3;
    const int arow_base = wm + (q & 1) * 8 + (lane & 7);
    const int acb_add   = q >> 1;
    const int brow_base = wn + (q >> 1) * 8 + (lane & 7);
    const int bcb_add   = q & 1;
    const int g = lane >> 2, cpair = (lane & 3) * 2;

    float acc[4][8][4];
#pragma unroll
    for (int i = 0; i < 4; i++)
#pragma unroll
        for (int j = 0; j < 8; j++)
#pragma unroll
            for (int c = 0; c < 4; c++) acc[i][j][c] = 0.0f;

    const int NCH = MS1 * 4;       // 32 chunks
    load_chunk(0, 0);

    for (int c = 0; c < NCH; c++) {
        int b = c & 1;
        if (c + 1 < NCH) {
            load_chunk(c + 1, b ^ 1);
            asm volatile("cp.async.wait_group 1;" ::: "memory");
        } else {
            asm volatile("cp.async.wait_group 0;" ::: "memory");
        }
        __syncthreads();

#pragma unroll
        for (int s = 0; s < 4; s++) {
            uint32_t af[4][4], bf[4][4];
#pragma unroll
            for (int i = 0; i < 4; i++) {
                int r = arow_base + i * 16;
                int cb = (2 * s + acb_add) ^ (r & 7);
                ldsm4(af[i], aoff[b] + (uint32_t)(r * 128 + cb * 16));
            }
#pragma unroll
            for (int j2 = 0; j2 < 4; j2++) {
                int r = brow_base + j2 * 16;
                int cb = (2 * s + bcb_add) ^ (r & 7);
                ldsm4(bf[j2], boff[b] + (uint32_t)(r * 128 + cb * 16));
            }
#pragma unroll
            for (int i = 0; i < 4; i++)
#pragma unroll
                for (int j = 0; j < 8; j++)
                    mma_f16(acc[i][j], af[i], &bf[j >> 1][(j & 1) * 2]);
        }

        if ((c & 3) == 3) {
            int row0 = rowbase + (c >> 2) * MT;
#pragma unroll
            for (int j = 0; j < 8; j++) {
                int col = n0 + wn + j * 8 + cpair;
                float b0 = __ldg(bias + col), b1 = __ldg(bias + col + 1);
#pragma unroll
                for (int i = 0; i < 4; i++) {
                    int r = row0 + wm + i * 16 + g;
                    float v0 = fmaxf(acc[i][j][0] + b0, 0.0f);
                    float v1 = fmaxf(acc[i][j][1] + b1, 0.0f);
                    float v2 = fmaxf(acc[i][j][2] + b0, 0.0f);
                    float v3 = fmaxf(acc[i][j][3] + b1, 0.0f);
                    *reinterpret_cast<__half2*>(C + (size_t)r * D_H + col)
                        = __floats2half2_rn(v0, v1);
                    *reinterpret_cast<__half2*>(C + (size_t)(r + 8) * D_H + col)
                        = __floats2half2_rn(v2, v3);
                }
            }
#pragma unroll
            for (int i = 0; i < 4; i++)
#pragma unroll
                for (int j = 0; j < 8; j++)
#pragma unroll
                    for (int cc = 0; cc < 4; cc++) acc[i][j][cc] = 0.0f;
        }
        __syncthreads();
    }
}

// ===========================================================================
// GEMM2 multi-M (R15 champion): CTA = 4 m-tiles x 128 rows x 128 cols over
// K=512. 2-stage/2-sync ring; flat 32-chunk loop, epilogue each 8th chunk.
// ===========================================================================
__global__ void __launch_bounds__(128, 2) tc_gemm2(
    const __half* __restrict__ A, const __half* __restrict__ Bt,
    const float* __restrict__ bias, __half* __restrict__ C)
{
    extern __shared__ char smem[];
    uint32_t sb = smem_u32(smem);
    const int tid = threadIdx.x, wid = tid >> 5, lane = tid & 31;
    const int rowbase = blockIdx.y * (MS2 * MT);
    const int n0      = blockIdx.x * NTT;

    const uint32_t aoff[2] = { sb,              sb + STAGE_BYTES };
    const uint32_t boff[2] = { sb + TILE_BYTES, sb + STAGE_BYTES + TILE_BYTES };

    const int lr = tid >> 3;
    const int lc = tid & 7;
    const __half* Abase = A  + (size_t)rowbase * D_H + lc * 8;
    const __half* Bbase = Bt + (size_t)n0 * D_H + lc * 8;

    auto load_chunk = [&](int c, int bi) {   // c: mt=c>>3, kt=c&7
        const __half* Ap = Abase + (size_t)(c >> 3) * MT * D_H + (c & 7) * KC;
        const __half* Bp = Bbase + (c & 7) * KC;
#pragma unroll
        for (int i = 0; i < 8; i++) {
            int r = lr + i * 16;
            uint32_t so = (uint32_t)(r * 128 + ((lc ^ (r & 7)) << 4));
            cpa16(aoff[bi] + so, Ap + (size_t)r * D_H);
            cpa16(boff[bi] + so, Bp + (size_t)r * D_H);
        }
        asm volatile("cp.async.commit_group;" ::: "memory");
    };

    const int wm = (wid >> 1) * 64;
    const int wn = (wid & 1) * 64;
    const int q = lane >> 3;
    const int arow_base = wm + (q & 1) * 8 + (lane & 7);
    const int acb_add   = q >> 1;
    const int brow_base = wn + (q >> 1) * 8 + (lane & 7);
    const int bcb_add   = q & 1;
    const int g = lane >> 2, cpair = (lane & 3) * 2;

    float acc[4][8][4];
#pragma unroll
    for (int i = 0; i < 4; i++)
#pragma unroll
        for (int j = 0; j < 8; j++)
#pragma unroll
            for (int c = 0; c < 4; c++) acc[i][j][c] = 0.0f;

    const int NCH = MS2 * 8;       // 32 chunks
    load_chunk(0, 0);

    for (int c = 0; c < NCH; c++) {
        int b = c & 1;
        if (c + 1 < NCH) {
            load_chunk(c + 1, b ^ 1);
            asm volatile("cp.async.wait_group 1;" ::: "memory");
        } else {
            asm volatile("cp.async.wait_group 0;" ::: "memory");
        }
        __syncthreads();

#pragma unroll
        for (int s = 0; s < 4; s++) {
            uint32_t af[4][4], bf[4][4];
#pragma unroll
            for (int i = 0; i < 4; i++) {
                int r = arow_base + i * 16;
                int cb = (2 * s + acb_add) ^ (r & 7);
                ldsm4(af[i], aoff[b] + (uint32_t)(r * 128 + cb * 16));
            }
#pragma unroll
            for (int j2 = 0; j2 < 4; j2++) {
                int r = brow_base + j2 * 16;
                int cb = (2 * s + bcb_add) ^ (r & 7);
                ldsm4(bf[j2], boff[b] + (uint32_t)(r * 128 + cb * 16));
            }
#pragma unroll
            for (int i = 0; i < 4; i++)
#pragma unroll
                for (int j = 0; j < 8; j++)
                    mma_f16(acc[i][j], af[i], &bf[j >> 1][(j & 1) * 2]);
        }

        if ((c & 7) == 7) {
            int row0 = rowbase + (c >> 3) * MT;
#pragma unroll
            for (int j = 0; j < 8; j++) {
                int col = n0 + wn + j * 8 + cpair;
                float b0 = __ldg(bias + col), b1 = __ldg(bias + col + 1);
#pragma unroll
                for (int i = 0; i < 4; i++) {
                    int r = row0 + wm + i * 16 + g;
                    float v0 = acc[i][j][0] + b0, v1 = acc[i][j][1] + b1;
                    float v2 = acc[i][j][2] + b0, v3 = acc[i][j][3] + b1;
                    *reinterpret_cast<__half2*>(C + (size_t)r * D_OUT + col)
                        = __floats2half2_rn(v0, v1);
                    *reinterpret_cast<__half2*>(C + (size_t)(r + 8) * D_OUT + col)
                        = __floats2half2_rn(v2, v3);
                }
            }
#pragma unroll
            for (int i = 0; i < 4; i++)
#pragma unroll
                for (int j = 0; j < 8; j++)
#pragma unroll
                    for (int cc = 0; cc < 4; cc++) acc[i][j][cc] = 0.0f;
        }
        __syncthreads();
    }
}

// ---------------------------------------------------------------------------
// Fused weight transposes (one launch): z=0 -> W1 (256x512), z=1 -> W2 (512x256)
// ---------------------------------------------------------------------------
__global__ __launch_bounds__(256) void transpose_both_kernel(
    const float* __restrict__ W1, __half* __restrict__ W1T,
    const float* __restrict__ W2, __half* __restrict__ W2T)
{
    const float* W;  __half* WT;  int R, Cn;
    if (blockIdx.z == 0) { W = W1; WT = W1T; R = D_IN; Cn = D_H; }
    else                 { W = W2; WT = W2T; R = D_H;  Cn = D_OUT; }
    int bx = blockIdx.x * 32, by = blockIdx.y * 32;
    if (bx >= Cn || by >= R) return;

    __shared__ float t[32][33];
    int x = threadIdx.x & 31, y = threadIdx.x >> 5;
#pragma unroll
    for (int i = 0; i < 32; i += 8)
        t[y + i][x] = W[(size_t)(by + y + i) * Cn + bx + x];
    __syncthreads();
#pragma unroll
    for (int i = 0; i < 32; i += 8)
        WT[(size_t)(bx + y + i) * R + by + x] = __float2half_rn(t[x][y + i]);
}

// ---------------------------------------------------------------------------
// LayerNorm (one warp/row), fp16 output
// ---------------------------------------------------------------------------
__global__ __launch_bounds__(256) void ln_kernel(
    const float* __restrict__ state, const float* __restrict__ nbrs,
    const float* __restrict__ gamma, const float* __restrict__ beta,
    __half* __restrict__ Xn, int B)
{
    int row  = blockIdx.x * 8 + (threadIdx.x >> 5);
    int lane = threadIdx.x & 31;
    const float* x = (row < B) ? state + (size_t)row * D_IN
                               : nbrs + (size_t)(row - B) * D_IN;
    float4 v0 = ((const float4*)x)[lane];
    float4 v1 = ((const float4*)x)[lane + 32];

    float s  = v0.x + v0.y + v0.z + v0.w + v1.x + v1.y + v1.z + v1.w;
    float ss = v0.x*v0.x + v0.y*v0.y + v0.z*v0.z + v0.w*v0.w
             + v1.x*v1.x + v1.y*v1.y + v1.z*v1.z + v1.w*v1.w;
#pragma unroll
    for (int o = 16; o; o >>= 1) {
        s  += __shfl_xor_sync(0xFFFFFFFFu, s,  o);
        ss += __shfl_xor_sync(0xFFFFFFFFu, ss, o);
    }
    float mu   = s * (1.0f / D_IN);
    float var  = ss * (1.0f / D_IN) - mu * mu;
    float rstd = rsqrtf(var + 1e-5f);

    float4 g0 = ((const float4*)gamma)[lane];
    float4 g1 = ((const float4*)gamma)[lane + 32];
    float4 be0 = ((const float4*)beta)[lane];
    float4 be1 = ((const float4*)beta)[lane + 32];

    __half2 h0 = __floats2half2_rn((v0.x - mu) * rstd * g0.x + be0.x,
                                   (v0.y - mu) * rstd * g0.y + be0.y);
    __half2 h1 = __floats2half2_rn((v0.z - mu) * rstd * g0.z + be0.z,
                                   (v0.w - mu) * rstd * g0.w + be0.w);
    __half2 h2 = __floats2half2_rn((v1.x - mu) * rstd * g1.x + be1.x,
                                   (v1.y - mu) * rstd * g1.y + be1.y);
    __half2 h3 = __floats2half2_rn((v1.z - mu) * rstd * g1.z + be1.z,
                                   (v1.w - mu) * rstd * g1.w + be1.w);

    __half* dst = Xn + (size_t)row * D_IN;
    uint2 w0, w1;
    w0.x = *(uint32_t*)&h0;  w0.y = *(uint32_t*)&h1;
    w1.x = *(uint32_t*)&h2;  w1.y = *(uint32_t*)&h3;
    ((uint2*)dst)[lane]      = w0;
    ((uint2*)(dst + 128))[lane] = w1;
}

// ---------------------------------------------------------------------------
// Attention aggregation (one warp/batch element), fp16 F, fp32 math/output.
// ---------------------------------------------------------------------------
__global__ __launch_bounds__(256) void attn_kernel(
    const __half* __restrict__ F, const float* __restrict__ aw,
    const float* __restrict__ ab_ptr, float* __restrict__ out, int B)
{
    int b    = blockIdx.x * 8 + (threadIdx.x >> 5);
    int lane = threadIdx.x & 31;
    float ab = ab_ptr[0];

    float4 w0 = ((const float4*)aw)[lane * 2];
    float4 w1 = ((const float4*)aw)[lane * 2 + 1];

    uint4 lv = ((const uint4*)(F + (size_t)b * D_OUT))[lane];
    float2 l0 = __half22float2(*(__half2*)&lv.x);
    float2 l1 = __half22float2(*(__half2*)&lv.y);
    float2 l2 = __half22float2(*(__half2*)&lv.z);
    float2 l3 = __half22float2(*(__half2*)&lv.w);

    uint4 nf[NB];
    float sc[NB];
#pragma unroll
    for (int n = 0; n < NB; n++) {
        nf[n] = ((const uint4*)(F + ((size_t)(1 + n) * B + b) * D_OUT))[lane];
        float2 a0 = __half22float2(*(__half2*)&nf[n].x);
        float2 a1 = __half22float2(*(__half2*)&nf[n].y);
        float2 a2 = __half22float2(*(__half2*)&nf[n].z);
        float2 a3 = __half22float2(*(__half2*)&nf[n].w);
        float d = a0.x * w0.x + a0.y * w0.y + a1.x * w0.z + a1.y * w0.w
                + a2.x * w1.x + a2.y * w1.y + a3.x * w1.z + a3.y * w1.w;
#pragma unroll
        for (int o = 16; o; o >>= 1) d += __shfl_xor_sync(0xFFFFFFFFu, d, o);
        sc[n] = d + ab;
    }

    float mx = sc[0];
#pragma unroll
    for (int n = 1; n < NB; n++) mx = fmaxf(mx, sc[n]);
    float se = 0.0f;
#pragma unroll
    for (int n = 0; n < NB; n++) { sc[n] = expf(sc[n] - mx); se += sc[n]; }
    float inv = 1.0f / se;

    float o0 = l0.x, o1 = l0.y, o2 = l1.x, o3 = l1.y;
    float o4 = l2.x, o5 = l2.y, o6 = l3.x, o7 = l3.y;
#pragma unroll
    for (int n = 0; n < NB; n++) {
        float wn = sc[n] * inv;
        float2 a0 = __half22float2(*(__half2*)&nf[n].x);
        float2 a1 = __half22float2(*(__half2*)&nf[n].y);
        float2 a2 = __half22float2(*(__half2*)&nf[n].z);
        float2 a3 = __half22float2(*(__half2*)&nf[n].w);
        o0 = fmaf(wn, a0.x, o0);  o1 = fmaf(wn, a0.y, o1);
        o2 = fmaf(wn, a1.x, o2);  o3 = fmaf(wn, a1.y, o3);
        o4 = fmaf(wn, a2.x, o4);  o5 = fmaf(wn, a2.y, o5);
        o6 = fmaf(wn, a3.x, o6);  o7 = fmaf(wn, a3.y, o7);
    }
    float* dst = out + (size_t)b * D_OUT;
    float4 r0 = { o0, o1, o2, o3 }, r1 = { o4, o5, o6, o7 };
    ((float4*)dst)[lane * 2]     = r0;
    ((float4*)dst)[lane * 2 + 1] = r1;
}

// ---------------------------------------------------------------------------
extern "C" void kernel_launch(void* const* d_in, const int* in_sizes, int n_in,
                              void* d_out, int out_size)
{
    const float* state = (const float*)d_in[0];
    const float* nbrs  = (const float*)d_in[1];
    const float* gamma = (const float*)d_in[2];
    const float* beta  = (const float*)d_in[3];
    const float* W1    = (const float*)d_in[4];
    const float* b1    = (const float*)d_in[5];
    const float* W2    = (const float*)d_in[6];
    const float* b2    = (const float*)d_in[7];
    const float* aw    = (const float*)d_in[8];
    const float* ab    = (const float*)d_in[9];
    float* out = (float*)d_out;

    int B = in_sizes[0] / D_IN;   // 32768
    int R = 9 * B;                // 294912

    __half *Xn, *H, *F, *W1T, *W2T;
    cudaGetSymbolAddress((void**)&Xn,  g_Xn);
    cudaGetSymbolAddress((void**)&H,   g_H);
    cudaGetSymbolAddress((void**)&F,   g_F);
    cudaGetSymbolAddress((void**)&W1T, g_W1T);
    cudaGetSymbolAddress((void**)&W2T, g_W2T);

    cudaFuncSetAttribute(tc_gemm1, cudaFuncAttributeMaxDynamicSharedMemorySize, SM_TOTAL);
    cudaFuncSetAttribute(tc_gemm2, cudaFuncAttributeMaxDynamicSharedMemorySize, SM_TOTAL);

    transpose_both_kernel<<<dim3(16, 16, 2), 256>>>(W1, W1T, W2, W2T);
    ln_kernel<<<R / 8, 256>>>(state, nbrs, gamma, beta, Xn, B);

    // H = h(relu(Xn @ W1 + b1)) — streaming, 8 m-tiles per CTA (32 chunks)
    tc_gemm1<<<dim3(D_H / NTT, R / (MS1 * MT)), 128, SM_TOTAL>>>(Xn, W1T, b1, H);
    // F = h(H @ W2 + b2) — streaming, 4 m-tiles per CTA (32 chunks)
    tc_gemm2<<<dim3(D_OUT / NTT, R / (MS2 * MT)), 128, SM_TOTAL>>>(H, W2T, b2, F);

    attn_kernel<<<B / 8, 256>>>(F, aw, ab, out, B);
}